// round 1
// baseline (speedup 1.0000x reference)
#include <cuda_runtime.h>
#include <cuda_bf16.h>

#define NBATCH 1024
#define MDIM 64
#define CDIM 4
#define TSTEPS 100
#define CLIPMAX 1e10f

// One CTA per batch element n. 64 threads, thread i owns patch-row i.
// Entire 100-step time loop runs inside the kernel; only per-step cross-thread
// data is p[64] (infection probs), exchanged via tiny SMEM + 2 barriers.
__global__ __launch_bounds__(64)
void metapop_kernel(const float* __restrict__ R,
                    const float* __restrict__ T,
                    const float* __restrict__ rho0,
                    const float* __restrict__ beta,
                    float* __restrict__ out)
{
    __shared__ float sR[MDIM * MDIM];   // staging for R[n]
    __shared__ float sinv[MDIM];        // 1/ntot[j]
    __shared__ float sT[CDIM * CDIM];
    __shared__ __align__(16) float sp[MDIM];

    const int n = blockIdx.x;
    const int i = threadIdx.x;          // 0..63

    // ---- stage R[n] into smem (coalesced float4) ----
    {
        const float4* Rg = (const float4*)(R + (size_t)n * MDIM * MDIM);
        float4* sR4 = (float4*)sR;
        for (int k = i; k < MDIM * MDIM / 4; k += 64) sR4[k] = Rg[k];
    }
    if (i < CDIM * CDIM) sT[i] = T[(size_t)n * CDIM * CDIM + i];
    __syncthreads();

    // ---- ntot[j] = sum_i R[n,i,j] (loop invariant), store reciprocal ----
    {
        float s = 0.0f;
        #pragma unroll
        for (int r = 0; r < MDIM; r++) s += sR[r * MDIM + i];
        sinv[i] = 1.0f / s;
    }
    __syncthreads();

    // ---- copy own R row into registers (for p -> new_inf matvec) ----
    float Rrow[MDIM];
    #pragma unroll
    for (int k = 0; k < MDIM; k++) Rrow[k] = sR[i * MDIM + k];

    // ---- gather Rt row and fold in 1/ntot:  Rtd[j] = Rt[n,i,j] * inv_ntot[j]
    // Rt[n,i,j] = R[(i&15)*64 + j, (n&15)*4 + (i>>4), n>>4]
    // (derived from jnp.transpose(R).reshape(N,M,M,1))
    float Rtd[MDIM];
    {
        const int b = (n & 15) * 4 + (i >> 4);
        const int a = n >> 4;
        const int cbase = (i & 15) * 64;
        const size_t off = (size_t)b * MDIM + a;
        #pragma unroll
        for (int j = 0; j < MDIM; j++) {
            Rtd[j] = R[(size_t)(cbase + j) * (MDIM * MDIM) + off] * sinv[j];
        }
    }

    const float bet = beta[n];

    // ---- rho row in registers ----
    float rho[CDIM];
    {
        const float4 r0 = *(const float4*)(rho0 + ((size_t)n * MDIM + i) * CDIM);
        rho[0] = r0.x; rho[1] = r0.y; rho[2] = r0.z; rho[3] = r0.w;
    }

    float4* out4 = (float4*)out;

    for (int t = 0; t < TSTEPS; t++) {
        // trajectory records the PRE-update state
        out4[((size_t)t * NBATCH + n) * MDIM + i] =
            make_float4(rho[0], rho[1], rho[2], rho[3]);

        // p_i = 1 - prod_j (1 - beta*rho[i,1]*Rt[i,j]/ntot[j])
        // (identical to 1 - exp(sum log(1-x)), no MUFU needed)
        const float coef = bet * rho[1];
        float pr0 = 1.0f, pr1 = 1.0f, pr2 = 1.0f, pr3 = 1.0f;
        #pragma unroll
        for (int j = 0; j < MDIM; j += 4) {
            pr0 *= fmaf(-coef, Rtd[j + 0], 1.0f);
            pr1 *= fmaf(-coef, Rtd[j + 1], 1.0f);
            pr2 *= fmaf(-coef, Rtd[j + 2], 1.0f);
            pr3 *= fmaf(-coef, Rtd[j + 3], 1.0f);
        }
        sp[i] = 1.0f - (pr0 * pr1) * (pr2 * pr3);
        __syncthreads();

        // new_inf_i = (1 - sum_c rho[i,c]) * sum_k R[i,k] * p[k]
        float a0 = 0.0f, a1 = 0.0f, a2 = 0.0f, a3 = 0.0f;
        const float4* sp4 = (const float4*)sp;
        #pragma unroll
        for (int k4 = 0; k4 < MDIM / 4; k4++) {
            const float4 p4 = sp4[k4];
            a0 = fmaf(Rrow[k4 * 4 + 0], p4.x, a0);
            a1 = fmaf(Rrow[k4 * 4 + 1], p4.y, a1);
            a2 = fmaf(Rrow[k4 * 4 + 2], p4.z, a2);
            a3 = fmaf(Rrow[k4 * 4 + 3], p4.w, a3);
        }
        const float newinf =
            (1.0f - ((rho[0] + rho[1]) + (rho[2] + rho[3]))) * ((a0 + a1) + (a2 + a3));

        // rho_new[l] = sum_k rho[k]*T[k,l] + (l==0)*newinf, clipped to [0, 1e10]
        float nr[CDIM];
        #pragma unroll
        for (int l = 0; l < CDIM; l++) {
            float v = (l == 0) ? newinf : 0.0f;
            #pragma unroll
            for (int k = 0; k < CDIM; k++) v = fmaf(rho[k], sT[k * CDIM + l], v);
            nr[l] = fminf(fmaxf(v, 0.0f), CLIPMAX);
        }
        #pragma unroll
        for (int l = 0; l < CDIM; l++) rho[l] = nr[l];

        __syncthreads();   // sp consumed by everyone before next step overwrites
    }
}

extern "C" void kernel_launch(void* const* d_in, const int* in_sizes, int n_in,
                              void* d_out, int out_size)
{
    const float* R    = (const float*)d_in[0];   // (1024, 64, 64)
    const float* T    = (const float*)d_in[1];   // (1024, 4, 4)
    const float* rho0 = (const float*)d_in[2];   // (1024, 64, 4)
    const float* beta = (const float*)d_in[3];   // (1024,)
    float* out = (float*)d_out;                  // (100, 1024, 64, 4)

    metapop_kernel<<<NBATCH, MDIM>>>(R, T, rho0, beta, out);
}

// round 3
// speedup vs baseline: 1.1835x; 1.1835x over previous
#include <cuda_runtime.h>
#include <cuda_bf16.h>

#define NBATCH 1024
#define MDIM 64
#define CDIM 4
#define TSTEPS 100
#define CLIPMAX 1e10f

// ---------------- packed f32x2 helpers (Blackwell FFMA2 path) ----------------
__device__ __forceinline__ unsigned long long pk2(float lo, float hi) {
    unsigned long long r;
    asm("mov.b64 %0, {%1, %2};" : "=l"(r) : "f"(lo), "f"(hi));
    return r;
}
__device__ __forceinline__ void upk2(unsigned long long v, float& lo, float& hi) {
    asm("mov.b64 {%0, %1}, %2;" : "=f"(lo), "=f"(hi) : "l"(v));
}
__device__ __forceinline__ unsigned long long fma2(unsigned long long a,
                                                   unsigned long long b,
                                                   unsigned long long c) {
    unsigned long long d;
    asm("fma.rn.f32x2 %0, %1, %2, %3;" : "=l"(d) : "l"(a), "l"(b), "l"(c));
    return d;
}
__device__ __forceinline__ unsigned long long mul2(unsigned long long a,
                                                   unsigned long long b) {
    unsigned long long d;
    asm("mul.rn.f32x2 %0, %1, %2;" : "=l"(d) : "l"(a), "l"(b));
    return d;
}
__device__ __forceinline__ unsigned long long add2(unsigned long long a,
                                                   unsigned long long b) {
    unsigned long long d;
    asm("add.rn.f32x2 %0, %1, %2;" : "=l"(d) : "l"(a), "l"(b));
    return d;
}

// One CTA per batch element n. 64 threads, thread i owns patch-row i.
// 100-step time loop inside the kernel; per-step cross-thread exchange is
// p[64] via double-buffered SMEM (1 barrier per step).
__global__ __launch_bounds__(64)
void metapop_kernel(const float* __restrict__ R,
                    const float* __restrict__ T,
                    const float* __restrict__ rho0,
                    const float* __restrict__ beta,
                    float* __restrict__ out)
{
    __shared__ float sR[MDIM * MDIM];
    __shared__ float sinv[MDIM];
    __shared__ float sT[CDIM * CDIM];
    __shared__ __align__(16) float sp[2][MDIM];   // double-buffered p

    const int n = blockIdx.x;
    const int i = threadIdx.x;

    // ---- stage R[n] into smem (coalesced float4) ----
    {
        const float4* Rg = (const float4*)(R + (size_t)n * MDIM * MDIM);
        float4* sR4 = (float4*)sR;
        for (int k = i; k < MDIM * MDIM / 4; k += 64) sR4[k] = Rg[k];
    }
    if (i < CDIM * CDIM) sT[i] = T[(size_t)n * CDIM * CDIM + i];
    __syncthreads();

    // ---- ntot[j] = sum_i R[n,i,j] (loop invariant); store reciprocal ----
    {
        float s = 0.0f;
        #pragma unroll
        for (int r = 0; r < MDIM; r++) s += sR[r * MDIM + i];
        sinv[i] = 1.0f / s;
    }
    __syncthreads();

    // ---- own R row -> packed register pairs (for matvec) ----
    unsigned long long Rrow2[MDIM / 2];
    #pragma unroll
    for (int k = 0; k < MDIM / 2; k++)
        Rrow2[k] = pk2(sR[i * MDIM + 2 * k], sR[i * MDIM + 2 * k + 1]);

    // ---- gather Rt row, fold 1/ntot, then pair-compress:
    // Rt[n,i,j] = R[(i&15)*64 + j, (n&15)*4 + (i>>4), n>>4]
    // For j-pair (j0,j1): (1-c*x0)(1-c*x1) = 1 - c*(x0+x1) + c^2*(x0*x1)
    // Store s2[g] = (s_pair0, s_pair1), q2[g] = (q_pair0, q_pair1), g covers 4 j's.
    unsigned long long s2[MDIM / 4], q2[MDIM / 4];
    {
        const int b = (n & 15) * 4 + (i >> 4);
        const int a = n >> 4;
        const int cbase = (i & 15) * 64;
        const size_t off = (size_t)b * MDIM + a;
        float Rtd[MDIM];
        #pragma unroll
        for (int j = 0; j < MDIM; j++)
            Rtd[j] = R[(size_t)(cbase + j) * (MDIM * MDIM) + off] * sinv[j];
        #pragma unroll
        for (int g = 0; g < MDIM / 4; g++) {
            const float x0 = Rtd[4 * g + 0], x1 = Rtd[4 * g + 1];
            const float x2 = Rtd[4 * g + 2], x3 = Rtd[4 * g + 3];
            s2[g] = pk2(x0 + x1, x2 + x3);
            q2[g] = pk2(x0 * x1, x2 * x3);
        }
    }

    const float bet = beta[n];
    const unsigned long long ones2 = pk2(1.0f, 1.0f);

    float rho[CDIM];
    {
        const float4 r0 = *(const float4*)(rho0 + ((size_t)n * MDIM + i) * CDIM);
        rho[0] = r0.x; rho[1] = r0.y; rho[2] = r0.z; rho[3] = r0.w;
    }

    float4* out4 = (float4*)out;

    for (int t = 0; t < TSTEPS; t++) {
        // trajectory records the PRE-update state
        out4[((size_t)t * NBATCH + n) * MDIM + i] =
            make_float4(rho[0], rho[1], rho[2], rho[3]);

        // p_i = 1 - prod_j (1 - c*Rtd[j]),  c = beta*rho[i,1]
        // pairwise-expanded: per 4 j's -> 2 packed fma + 1 packed mul
        const float coef = bet * rho[1];
        const float csq  = coef * coef;
        const unsigned long long nc2 = pk2(-coef, -coef);
        const unsigned long long cs2 = pk2(csq, csq);

        unsigned long long pr0 = ones2, pr1 = ones2, pr2 = ones2, pr3 = ones2;
        #pragma unroll
        for (int g = 0; g < MDIM / 4; g += 4) {
            pr0 = mul2(pr0, fma2(cs2, q2[g + 0], fma2(nc2, s2[g + 0], ones2)));
            pr1 = mul2(pr1, fma2(cs2, q2[g + 1], fma2(nc2, s2[g + 1], ones2)));
            pr2 = mul2(pr2, fma2(cs2, q2[g + 2], fma2(nc2, s2[g + 2], ones2)));
            pr3 = mul2(pr3, fma2(cs2, q2[g + 3], fma2(nc2, s2[g + 3], ones2)));
        }
        unsigned long long m = mul2(mul2(pr0, pr1), mul2(pr2, pr3));
        float mx, my; upk2(m, mx, my);

        const int buf = t & 1;
        sp[buf][i] = 1.0f - mx * my;
        __syncthreads();

        // dot_i = sum_k R[i,k] * p[k]   (uniform smem address -> broadcast LDS)
        // ulonglong2 = 4 floats per iteration -> MDIM/4 = 16 iterations total.
        unsigned long long a0 = 0ULL, a1 = 0ULL, a2 = 0ULL, a3 = 0ULL;
        const ulonglong2* spp = (const ulonglong2*)sp[buf];
        #pragma unroll
        for (int q = 0; q < MDIM / 4; q++) {
            const ulonglong2 pv = spp[q];
            if (q & 1) {
                a2 = fma2(Rrow2[2 * q + 0], pv.x, a2);
                a3 = fma2(Rrow2[2 * q + 1], pv.y, a3);
            } else {
                a0 = fma2(Rrow2[2 * q + 0], pv.x, a0);
                a1 = fma2(Rrow2[2 * q + 1], pv.y, a1);
            }
        }
        unsigned long long aa = add2(add2(a0, a1), add2(a2, a3));
        float ax, ay; upk2(aa, ax, ay);
        const float dot = ax + ay;

        const float newinf =
            (1.0f - ((rho[0] + rho[1]) + (rho[2] + rho[3]))) * dot;

        // rho_new[l] = sum_k rho[k]*T[k,l] + (l==0)*newinf, clipped
        float nr[CDIM];
        #pragma unroll
        for (int l = 0; l < CDIM; l++) {
            float v = (l == 0) ? newinf : 0.0f;
            #pragma unroll
            for (int k = 0; k < CDIM; k++) v = fmaf(rho[k], sT[k * CDIM + l], v);
            nr[l] = fminf(fmaxf(v, 0.0f), CLIPMAX);
        }
        #pragma unroll
        for (int l = 0; l < CDIM; l++) rho[l] = nr[l];
        // no second barrier: next step writes sp[buf^1]
    }
}

extern "C" void kernel_launch(void* const* d_in, const int* in_sizes, int n_in,
                              void* d_out, int out_size)
{
    const float* R    = (const float*)d_in[0];   // (1024, 64, 64)
    const float* T    = (const float*)d_in[1];   // (1024, 4, 4)
    const float* rho0 = (const float*)d_in[2];   // (1024, 64, 4)
    const float* beta = (const float*)d_in[3];   // (1024,)
    float* out = (float*)d_out;                  // (100, 1024, 64, 4)

    metapop_kernel<<<NBATCH, MDIM>>>(R, T, rho0, beta, out);
}